// round 16
// baseline (speedup 1.0000x reference)
#include <cuda_runtime.h>
#include <cuda_bf16.h>

#define Bb   16
#define Nn   8
#define Tt   65536
#define CPB  18            // chunks (blocks) per batch
#define TPB  128
#define NVALS 80           // 64 gram + 8 sum(x^2) + 8 sum(y^2)
#define GRID (Bb * CPB)    // 288 blocks = one wave (<=2/SM on 148 SMs)
#define COLS (Tt / 4)      // 16384 float4 columns per row

// Partials [batch][val][chunk] -> Phase A reads 18 contiguous floats per val.
// Per-batch completion counters. No float atomics -> deterministic.
__device__ float g_partial[Bb * NVALS * CPB];
__device__ unsigned int g_cnt[Bb];

__device__ __forceinline__ float dot4(float4 a, float4 b) {
    return a.x * b.x + a.y * b.y + a.z * b.z + a.w * b.w;
}

// ---------------------------------------------------------------------------
// Kernel 1: R2/R15 gram body (proven codegen) on a 288-block one-wave grid,
// 18 blocks per batch, balanced column ranges (16384 = 18*910 + 4).
// Ends with release-fence + per-batch counter bump so the concurrently
// resident sink can process each batch AS IT COMPLETES.
// ---------------------------------------------------------------------------
__global__ __launch_bounds__(TPB) void k_gram(const float* __restrict__ inp,
                                              const float* __restrict__ tgt) {
    const int bid   = blockIdx.x;
    const int b     = bid / CPB;
    const int local = bid % CPB;
    const int tid   = threadIdx.x;

    const int chunk = COLS / CPB, rem = COLS % CPB;     // 910, 4
    const int start = local * chunk + (local < rem ? local : rem);
    const int end   = start + chunk + (local < rem ? 1 : 0);

    const float4* ip = reinterpret_cast<const float4*>(inp) + (size_t)b * Nn * COLS;
    const float4* tp = reinterpret_cast<const float4*>(tgt) + (size_t)b * Nn * COLS;

    float acc[NVALS];
#pragma unroll
    for (int v = 0; v < NVALS; v++) acc[v] = 0.f;

    for (int idx = start + tid; idx < end; idx += TPB) {
        float4 av[Nn], bv[Nn];
#pragma unroll
        for (int i = 0; i < Nn; i++) av[i] = ip[i * COLS + idx];
#pragma unroll
        for (int j = 0; j < Nn; j++) bv[j] = tp[j * COLS + idx];
#pragma unroll
        for (int i = 0; i < Nn; i++) acc[64 + i] += dot4(av[i], av[i]);
#pragma unroll
        for (int j = 0; j < Nn; j++) acc[72 + j] += dot4(bv[j], bv[j]);
#pragma unroll
        for (int i = 0; i < Nn; i++)
#pragma unroll
            for (int j = 0; j < Nn; j++)
                acc[i * 8 + j] += dot4(av[i], bv[j]);
    }

    // Fixed-order reduction: warp shuffle then cross-warp via smem.
    __shared__ float sm[TPB / 32][NVALS];
    const int lane = tid & 31, warp = tid >> 5;
#pragma unroll
    for (int v = 0; v < NVALS; v++) {
        float x = acc[v];
#pragma unroll
        for (int off = 16; off; off >>= 1) x += __shfl_down_sync(0xffffffffu, x, off);
        if (lane == 0) sm[warp][v] = x;
    }
    __syncthreads();
    if (tid < NVALS) {
        float s = 0.f;
#pragma unroll
        for (int w = 0; w < TPB / 32; w++) s += sm[w][tid];
        g_partial[(b * NVALS + tid) * CPB + local] = s;   // [b][val][chunk]
    }

    // Publish this batch-chunk: release, then bump the batch counter.
    __syncthreads();
    if (tid == 0) {
        __threadfence();
        atomicAdd(&g_cnt[b], 1u);
    }
}

// ---------------------------------------------------------------------------
// Kernel 2: per-batch streaming sink (launched concurrently with gram).
// Warp w owns batch w: spins on g_cnt[w]==18, reduces its 80 vals (18
// contiguous floats each), runs the R5-proven all-shuffle linear Sinkhorn,
// writes pattern; one final block barrier for the loss mean. Everything per
// batch overlaps gram's remaining batches.
// ---------------------------------------------------------------------------
__global__ __launch_bounds__(512) void k_sink(float* __restrict__ out, int out_size) {
    __shared__ float G[Bb][NVALS];
    __shared__ float bloss[Bb];

    const int tid = threadIdx.x;
    const int w   = tid >> 5;          // batch
    const int l   = tid & 31;          // lane

    // Wait for THIS batch only.
    if (l == 0) {
        volatile unsigned int* cnt = &g_cnt[w];
        while (*cnt < CPB) { __nanosleep(64); }
    }
    __syncwarp();
    __threadfence();                   // acquire this batch's partials

    // Phase A (per warp): lane l sums vals l, l+32, and (l<16) l+64.
#pragma unroll
    for (int rep = 0; rep < 3; rep++) {
        const int v = l + rep * 32;
        if (v < NVALS) {
            const float* p = &g_partial[(w * NVALS + v) * CPB];
            float s = 0.f;
#pragma unroll
            for (int k = 0; k < CPB; k++) s += p[k];
            G[w][v] = s;
        }
    }
    __syncwarp();

    // Phase B: lanes = (i0 = l>>3 and i0+4) x (j = l&7).
    const int j  = l & 7;
    const int i0 = l >> 3;
    const int i1 = i0 + 4;
    const float invT = 1.0f / (float)Tt;

    const float L0 = (G[w][64 + i0] + G[w][72 + j] - 2.f * G[w][i0 * 8 + j]) * invT;
    const float L1 = (G[w][64 + i1] + G[w][72 + j] - 2.f * G[w][i1 * 8 + j]) * invT;
    float p0 = __expf(-L0), p1 = __expf(-L1);   // P = exp(-COLDNESS*L)

    // Linear-domain Sinkhorn: column-normalize then row-normalize, 10x.
#pragma unroll
    for (int it = 0; it < 10; it++) {
        float s = p0 + p1;
        s += __shfl_xor_sync(0xffffffffu, s, 8);
        s += __shfl_xor_sync(0xffffffffu, s, 16);
        const float r = __fdividef(1.f, s);
        p0 *= r;
        p1 *= r;

        float s0 = p0, s1 = p1;
        s0 += __shfl_xor_sync(0xffffffffu, s0, 1);
        s1 += __shfl_xor_sync(0xffffffffu, s1, 1);
        s0 += __shfl_xor_sync(0xffffffffu, s0, 2);
        s1 += __shfl_xor_sync(0xffffffffu, s1, 2);
        s0 += __shfl_xor_sync(0xffffffffu, s0, 4);
        s1 += __shfl_xor_sync(0xffffffffu, s1, 4);
        p0 *= __fdividef(1.f, s0);
        p1 *= __fdividef(1.f, s1);
    }

    // Loss partial for this batch.
    float lp = (L0 + __logf(p0)) * p0 + (L1 + __logf(p1)) * p1;
#pragma unroll
    for (int off = 16; off; off >>= 1) lp += __shfl_xor_sync(0xffffffffu, lp, off);
    if (l == 0) bloss[w] = lp;

    // Argmax over j per row, first occurrence on ties (matches jnp.argmax).
    float v0 = p0, v1 = p1;
    int   a0 = j,  a1 = j;
#pragma unroll
    for (int off = 1; off <= 4; off <<= 1) {
        float ov = __shfl_xor_sync(0xffffffffu, v0, off);
        int   oa = __shfl_xor_sync(0xffffffffu, a0, off);
        if (ov > v0 || (ov == v0 && oa < a0)) { v0 = ov; a0 = oa; }
        ov = __shfl_xor_sync(0xffffffffu, v1, off);
        oa = __shfl_xor_sync(0xffffffffu, a1, off);
        if (ov > v1 || (ov == v1 && oa < a1)) { v1 = ov; a1 = oa; }
    }
    if (out_size >= 1 + Bb * Nn && j == 0) {
        out[1 + w * Nn + i0] = (float)a0;
        out[1 + w * Nn + i1] = (float)a1;
    }

    // Final loss mean across batches + counter reset for graph replay.
    __syncthreads();
    if (tid == 0) {
        float s = 0.f;
#pragma unroll
        for (int b = 0; b < Bb; b++) s += bloss[b];
        out[0] = s * (1.0f / (float)Bb);
    }
    if (tid < Bb) g_cnt[tid] = 0;
}

// ---------------------------------------------------------------------------
// Forked launch (R14/R15-proven): sink runs concurrently with gram;
// device-side per-batch counters are the real synchronization.
// ---------------------------------------------------------------------------
extern "C" void kernel_launch(void* const* d_in, const int* in_sizes, int n_in,
                              void* d_out, int out_size) {
    const float* inp = (const float*)d_in[0];
    const float* tgt = (const float*)d_in[1];

    static cudaStream_t s2 = nullptr;
    static cudaEvent_t ev_fork = nullptr, ev_join = nullptr;
    if (s2 == nullptr) {
        cudaStreamCreateWithFlags(&s2, cudaStreamNonBlocking);
        cudaEventCreateWithFlags(&ev_fork, cudaEventDisableTiming);
        cudaEventCreateWithFlags(&ev_join, cudaEventDisableTiming);
    }

    cudaEventRecord(ev_fork, 0);
    cudaStreamWaitEvent(s2, ev_fork, 0);

    k_gram<<<GRID, TPB>>>(inp, tgt);
    k_sink<<<1, 512, 0, s2>>>((float*)d_out, out_size);

    cudaEventRecord(ev_join, s2);
    cudaStreamWaitEvent(0, ev_join, 0);
}

// round 17
// speedup vs baseline: 1.6672x; 1.6672x over previous
#include <cuda_runtime.h>
#include <cuda_bf16.h>

#define Bb   16
#define Nn   8
#define Tt   65536
#define TPB  128
#define NVALS 80           // 64 gram + 8 sum(x^2) + 8 sum(y^2)
#define GRID 294           // 147 SMs x 2 blocks: leaves 1 SM slot for the sink
#define NB_HI 19           // blocks for batches 0..5
#define NB_LO 18           // blocks for batches 6..15  (6*19 + 10*18 = 294)
#define HI_B  6
#define COLS (Tt / 4)      // 16384 float4 columns per row

// Deterministic scratch (no float atomics). [block][val] layout (R2-proven).
__device__ float g_partial[GRID * NVALS];
__device__ unsigned int g_count = 0;

__device__ __forceinline__ float dot4(float4 a, float4 b) {
    return a.x * b.x + a.y * b.y + a.z * b.z + a.w * b.w;
}

// ---------------------------------------------------------------------------
// Kernel 1: R15 gram (proven 18.5us config) with GRID=294 so that ALL gram
// blocks PLUS the co-resident sink block fit in one wave (R15's 296 blocks
// exceeded the 147*2+1=295 slots by one -> a straggler block ran as a second
// wave). Inner body, reduction, and publish are R15-identical.
// ---------------------------------------------------------------------------
__global__ __launch_bounds__(TPB) void k_gram(const float* __restrict__ inp,
                                              const float* __restrict__ tgt) {
    const int bid = blockIdx.x;
    const int tid = threadIdx.x;

    int b, local, nb;
    if (bid < HI_B * NB_HI) { b = bid / NB_HI; local = bid % NB_HI; nb = NB_HI; }
    else { const int r = bid - HI_B * NB_HI; b = HI_B + r / NB_LO; local = r % NB_LO; nb = NB_LO; }

    const int chunk = COLS / nb, rem = COLS % nb;
    const int start = local * chunk + (local < rem ? local : rem);
    const int end   = start + chunk + (local < rem ? 1 : 0);

    const float4* ip = reinterpret_cast<const float4*>(inp) + (size_t)b * Nn * COLS;
    const float4* tp = reinterpret_cast<const float4*>(tgt) + (size_t)b * Nn * COLS;

    float acc[NVALS];
#pragma unroll
    for (int v = 0; v < NVALS; v++) acc[v] = 0.f;

    for (int idx = start + tid; idx < end; idx += TPB) {
        float4 av[Nn], bv[Nn];
#pragma unroll
        for (int i = 0; i < Nn; i++) av[i] = ip[i * COLS + idx];
#pragma unroll
        for (int j = 0; j < Nn; j++) bv[j] = tp[j * COLS + idx];
#pragma unroll
        for (int i = 0; i < Nn; i++) acc[64 + i] += dot4(av[i], av[i]);
#pragma unroll
        for (int j = 0; j < Nn; j++) acc[72 + j] += dot4(bv[j], bv[j]);
#pragma unroll
        for (int i = 0; i < Nn; i++)
#pragma unroll
            for (int j = 0; j < Nn; j++)
                acc[i * 8 + j] += dot4(av[i], bv[j]);
    }

    // Fixed-order reduction: warp shuffle then cross-warp via smem.
    __shared__ float sm[TPB / 32][NVALS];
    const int lane = tid & 31, warp = tid >> 5;
#pragma unroll
    for (int v = 0; v < NVALS; v++) {
        float x = acc[v];
#pragma unroll
        for (int off = 16; off; off >>= 1) x += __shfl_down_sync(0xffffffffu, x, off);
        if (lane == 0) sm[warp][v] = x;
    }
    __syncthreads();
    if (tid < NVALS) {
        float s = 0.f;
#pragma unroll
        for (int w = 0; w < TPB / 32; w++) s += sm[w][tid];
        g_partial[bid * NVALS + tid] = s;
    }

    // Publish: release partials, then signal completion (R14/R15-proven).
    __syncthreads();
    if (tid == 0) {
        __threadfence();
        atomicAdd(&g_count, 1u);
    }
}

// ---------------------------------------------------------------------------
// Kernel 2: R15 sink verbatim (single-thread spin — R16 proved multi-warp
// polling is poison). Phase A sums each batch's block range (19 or 18).
// ---------------------------------------------------------------------------
__global__ __launch_bounds__(512) void k_sink(float* __restrict__ out, int out_size) {
    if (threadIdx.x == 0) {
        volatile unsigned int* cnt = &g_count;
        while (*cnt < GRID) { __nanosleep(64); }
    }
    __syncthreads();
    __threadfence();   // acquire gram's partials

    __shared__ float G[Bb][NVALS];
    __shared__ float bloss[Bb];

    const int tid = threadIdx.x;

    // Phase A: 1280 (batch,value) outputs; per batch, its block range.
    for (int v = tid; v < Bb * NVALS; v += 512) {
        const int b = v / NVALS, val = v % NVALS;
        const int sb = (b < HI_B) ? b * NB_HI : HI_B * NB_HI + (b - HI_B) * NB_LO;
        const int nb = (b < HI_B) ? NB_HI : NB_LO;
        const float* p = &g_partial[sb * NVALS + val];
        float s = 0.f;
        for (int k = 0; k < nb; k++) s += p[k * NVALS];
        G[b][val] = s;
    }
    __syncthreads();

    // Phase B: warp w = batch w; lanes = (i0 = l>>3 and i0+4) x (j = l&7).
    const int w  = tid >> 5;
    const int l  = tid & 31;
    const int j  = l & 7;
    const int i0 = l >> 3;
    const int i1 = i0 + 4;
    const float invT = 1.0f / (float)Tt;

    if (w < Bb) {
        const float L0 = (G[w][64 + i0] + G[w][72 + j] - 2.f * G[w][i0 * 8 + j]) * invT;
        const float L1 = (G[w][64 + i1] + G[w][72 + j] - 2.f * G[w][i1 * 8 + j]) * invT;
        float p0 = __expf(-L0), p1 = __expf(-L1);   // P = exp(-COLDNESS*L)

        // Linear-domain Sinkhorn: column-normalize then row-normalize, 10x.
#pragma unroll
        for (int it = 0; it < 10; it++) {
            float s = p0 + p1;
            s += __shfl_xor_sync(0xffffffffu, s, 8);
            s += __shfl_xor_sync(0xffffffffu, s, 16);
            const float r = __fdividef(1.f, s);
            p0 *= r;
            p1 *= r;

            float s0 = p0, s1 = p1;
            s0 += __shfl_xor_sync(0xffffffffu, s0, 1);
            s1 += __shfl_xor_sync(0xffffffffu, s1, 1);
            s0 += __shfl_xor_sync(0xffffffffu, s0, 2);
            s1 += __shfl_xor_sync(0xffffffffu, s1, 2);
            s0 += __shfl_xor_sync(0xffffffffu, s0, 4);
            s1 += __shfl_xor_sync(0xffffffffu, s1, 4);
            p0 *= __fdividef(1.f, s0);
            p1 *= __fdividef(1.f, s1);
        }

        float lp = (L0 + __logf(p0)) * p0 + (L1 + __logf(p1)) * p1;
#pragma unroll
        for (int off = 16; off; off >>= 1) lp += __shfl_xor_sync(0xffffffffu, lp, off);
        if (l == 0) bloss[w] = lp;

        // Argmax over j per row, first occurrence on ties (matches jnp.argmax).
        float v0 = p0, v1 = p1;
        int   a0 = j,  a1 = j;
#pragma unroll
        for (int off = 1; off <= 4; off <<= 1) {
            float ov = __shfl_xor_sync(0xffffffffu, v0, off);
            int   oa = __shfl_xor_sync(0xffffffffu, a0, off);
            if (ov > v0 || (ov == v0 && oa < a0)) { v0 = ov; a0 = oa; }
            ov = __shfl_xor_sync(0xffffffffu, v1, off);
            oa = __shfl_xor_sync(0xffffffffu, a1, off);
            if (ov > v1 || (ov == v1 && oa < a1)) { v1 = ov; a1 = oa; }
        }
        if (out_size >= 1 + Bb * Nn && j == 0) {
            out[1 + w * Nn + i0] = (float)a0;
            out[1 + w * Nn + i1] = (float)a1;
        }
    }

    __syncthreads();
    if (tid == 0) {
        float s = 0.f;
#pragma unroll
        for (int b = 0; b < Bb; b++) s += bloss[b];
        out[0] = s * (1.0f / (float)Bb);
        g_count = 0;                      // reset for next replay
    }
}

// ---------------------------------------------------------------------------
// Forked launch (R14/R15-proven): sink runs concurrently with gram;
// device-side counter is the real synchronization.
// ---------------------------------------------------------------------------
extern "C" void kernel_launch(void* const* d_in, const int* in_sizes, int n_in,
                              void* d_out, int out_size) {
    const float* inp = (const float*)d_in[0];
    const float* tgt = (const float*)d_in[1];

    static cudaStream_t s2 = nullptr;
    static cudaEvent_t ev_fork = nullptr, ev_join = nullptr;
    if (s2 == nullptr) {
        cudaStreamCreateWithFlags(&s2, cudaStreamNonBlocking);
        cudaEventCreateWithFlags(&ev_fork, cudaEventDisableTiming);
        cudaEventCreateWithFlags(&ev_join, cudaEventDisableTiming);
    }

    cudaEventRecord(ev_fork, 0);
    cudaStreamWaitEvent(s2, ev_fork, 0);

    k_gram<<<GRID, TPB>>>(inp, tgt);
    k_sink<<<1, 512, 0, s2>>>((float*)d_out, out_size);

    cudaEventRecord(ev_join, s2);
    cudaStreamWaitEvent(0, ev_join, 0);
}